// round 6
// baseline (speedup 1.0000x reference)
#include <cuda_runtime.h>
#include <math.h>

#define NUM_USERS 100000
#define NUM_ITEMS 50000
#define NROWS     150000      // NUM_USERS + NUM_ITEMS
#define NPAD      150016      // padded row count (multiple of 128)
#define EMB       64
#define NEDGES    2400000
#define NLAYERS   3
#define NEG_SLOPE 0.01f

#define SCAN_CHUNK 2048
#define NUM_CHUNKS ((NROWS + SCAN_CHUNK - 1) / SCAN_CHUNK)   // 74

typedef unsigned long long u64;

// packed fp32x2 FMA (Blackwell; ptxas never auto-fuses -> inline PTX)
#define FMA2(d, a, b, c) \
    asm("fma.rn.f32x2 %0, %1, %2, %3;" : "=l"(d) : "l"(a), "l"(b), "l"(c))
#define PACK2(d, lo, hi) \
    asm("mov.b64 %0, {%1, %2};" : "=l"(d) : "f"(lo), "f"(hi))
#define UNPACK2(lo, hi, v) \
    asm("mov.b64 {%0, %1}, %2;" : "=f"(lo), "=f"(hi) : "l"(v))

// -------- persistent device scratch (no allocations allowed) --------
__device__ __align__(16) float g_egoA[NPAD * EMB];
__device__ __align__(16) float g_egoB[NPAD * EMB];
__device__ int   g_row_ptr[NROWS + 1];
__device__ int   g_cursor [NROWS];       // histogram counts, then scatter cursor
__device__ int   g_col [NEDGES];
__device__ float g_val [NEDGES];
__device__ int   g_bsum[NUM_CHUNKS];
__device__ int   g_boff[NUM_CHUNKS];

// ---------------------------------------------------------------
// CSR build
// ---------------------------------------------------------------
__global__ void k_hist(const int* __restrict__ rows, int n_edges) {
    int e = blockIdx.x * blockDim.x + threadIdx.x;
    if (e < n_edges) atomicAdd(&g_cursor[rows[e]], 1);
}

__global__ void k_scan_sums() {
    int b = blockIdx.x, t = threadIdx.x;
    int base = b * SCAN_CHUNK + t * 8;
    int s = 0;
#pragma unroll
    for (int i = 0; i < 8; i++) {
        int idx = base + i;
        if (idx < NROWS) s += g_cursor[idx];
    }
    __shared__ int sh[256];
    sh[t] = s;
    __syncthreads();
    for (int d = 128; d > 0; d >>= 1) {
        if (t < d) sh[t] += sh[t + d];
        __syncthreads();
    }
    if (t == 0) g_bsum[b] = sh[0];
}

__global__ void k_scan_top() {
    int t = threadIdx.x;
    __shared__ int sh[128];
    int v = (t < NUM_CHUNKS) ? g_bsum[t] : 0;
    sh[t] = v;
    __syncthreads();
    for (int d = 1; d < 128; d <<= 1) {
        int x = (t >= d) ? sh[t - d] : 0;
        __syncthreads();
        sh[t] += x;
        __syncthreads();
    }
    if (t < NUM_CHUNKS) g_boff[t] = sh[t] - v;
    if (t == NUM_CHUNKS - 1) g_row_ptr[NROWS] = sh[t];
}

__global__ void k_scan_final() {
    int b = blockIdx.x, t = threadIdx.x;
    int base = b * SCAN_CHUNK + t * 8;
    int v[8];
    int local = 0;
#pragma unroll
    for (int i = 0; i < 8; i++) {
        int idx = base + i;
        v[i] = (idx < NROWS) ? g_cursor[idx] : 0;
        local += v[i];
    }
    __shared__ int sh[256];
    sh[t] = local;
    __syncthreads();
    for (int d = 1; d < 256; d <<= 1) {
        int x = (t >= d) ? sh[t - d] : 0;
        __syncthreads();
        sh[t] += x;
        __syncthreads();
    }
    int exc = g_boff[b] + (t ? sh[t - 1] : 0);
#pragma unroll
    for (int i = 0; i < 8; i++) {
        int idx = base + i;
        if (idx < NROWS) {
            g_row_ptr[idx] = exc;
            g_cursor[idx]  = exc;
        }
        exc += v[i];
    }
}

__global__ void k_scatter(const int* __restrict__ rows,
                          const int* __restrict__ cols,
                          const float* __restrict__ vals, int n_edges) {
    int e = blockIdx.x * blockDim.x + threadIdx.x;
    if (e < n_edges) {
        int r = rows[e];
        int pos = atomicAdd(&g_cursor[r], 1);
        g_col[pos] = cols[e];
        g_val[pos] = vals[e];
    }
}

// ---------------------------------------------------------------
// setup: zero hist counters; egoA = [user_emb; item_emb]; out[:,0:64] = egoA
// ---------------------------------------------------------------
__global__ void k_setup(const float* __restrict__ user_emb,
                        const float* __restrict__ item_emb,
                        float* __restrict__ out) {
    int idx = blockIdx.x * blockDim.x + threadIdx.x;   // one float4 per thread
    if (idx < NROWS) g_cursor[idx] = 0;
    if (idx >= NROWS * 16) return;
    int r = idx >> 4;
    int c4 = idx & 15;
    float4 v;
    if (r < NUM_USERS)
        v = ((const float4*)&user_emb[r * EMB])[c4];
    else
        v = ((const float4*)&item_emb[(r - NUM_USERS) * EMB])[c4];
    ((float4*)&g_egoA[r * EMB])[c4] = v;
    ((float4*)&out[r * (EMB * (NLAYERS + 1))])[c4] = v;
}

// ---------------------------------------------------------------
// Fused layer: side = A @ ego_in (into shared), then
//   ego_out = lrelu(side@W1+b1) + lrelu((ego_in*side)@W2+b2)
//   out[:, (l+1)*64:(l+2)*64] = ego_out / max(||ego_out||, eps)
// 256 threads per 128 rows. Phase A: 8 warps x 16 rows, 4 rows concurrent.
// Phase C: thread computes 32 output cols of one row (f32x2 FMA).
// ---------------------------------------------------------------
__device__ __forceinline__ float lrelu(float a) {
    return (a > 0.f) ? a : NEG_SLOPE * a;
}

__global__ void __launch_bounds__(256)
k_layer(const float* __restrict__ egoIn, float* __restrict__ egoOut,
        const float* __restrict__ W1g, const float* __restrict__ b1g,
        const float* __restrict__ W2g, const float* __restrict__ b2g,
        float* __restrict__ out, int layer) {
    extern __shared__ float sh[];
    float* W1s   = sh;                 // 4096
    float* W2s   = sh + 4096;          // 4096
    float* b1s   = sh + 8192;          // 64
    float* b2s   = sh + 8256;          // 64
    float* ssq   = sh + 8320;          // 256
    float* sideS = sh + 8576;          // 128*65 = 8320
    float* uS    = sideS + 128 * 65;   // 8320
    // total 25216 floats = 100864 bytes

    int t = threadIdx.x;
    int base = blockIdx.x * 128;

    // weights -> shared (used after the A->B sync)
#pragma unroll 4
    for (int i = t; i < 1024; i += 256) {
        ((float4*)W1s)[i] = ((const float4*)W1g)[i];
        ((float4*)W2s)[i] = ((const float4*)W2g)[i];
    }
    if (t < 64) { b1s[t] = b1g[t]; b2s[t] = b2g[t]; }

    // ---- Phase A: SpMM into sideS. warp wid handles rows wid*16..wid*16+15,
    //      processed in 4 groups of 4 concurrent rows (MLP x4).
    //      NOTE: sideS rows have odd stride 65 -> scalar stores only
    //      (a float2 STS at odd-row offsets is 4B-aligned -> fault).
    {
        int wid = t >> 5, lane = t & 31;
#pragma unroll 1
        for (int g = 0; g < 4; g++) {
            int lr0 = wid * 16 + g * 4;       // local row of first in group
            int s0[4], len[4];
#pragma unroll
            for (int j = 0; j < 4; j++) {
                int r = base + lr0 + j;
                if (r < NROWS) {
                    int a = g_row_ptr[r];
                    s0[j] = a;
                    len[j] = g_row_ptr[r + 1] - a;
                } else { s0[j] = 0; len[j] = 0; }
            }
            float2 a0 = {0.f, 0.f}, a1 = {0.f, 0.f}, a2 = {0.f, 0.f}, a3 = {0.f, 0.f};
            int nmax = max(max(len[0], len[1]), max(len[2], len[3]));
            for (int i = 0; i < nmax; i++) {
                if (i < len[0]) {
                    int c = __ldg(&g_col[s0[0] + i]);
                    float v = __ldg(&g_val[s0[0] + i]);
                    float2 x = *(const float2*)&egoIn[c * EMB + lane * 2];
                    a0.x = fmaf(v, x.x, a0.x); a0.y = fmaf(v, x.y, a0.y);
                }
                if (i < len[1]) {
                    int c = __ldg(&g_col[s0[1] + i]);
                    float v = __ldg(&g_val[s0[1] + i]);
                    float2 x = *(const float2*)&egoIn[c * EMB + lane * 2];
                    a1.x = fmaf(v, x.x, a1.x); a1.y = fmaf(v, x.y, a1.y);
                }
                if (i < len[2]) {
                    int c = __ldg(&g_col[s0[2] + i]);
                    float v = __ldg(&g_val[s0[2] + i]);
                    float2 x = *(const float2*)&egoIn[c * EMB + lane * 2];
                    a2.x = fmaf(v, x.x, a2.x); a2.y = fmaf(v, x.y, a2.y);
                }
                if (i < len[3]) {
                    int c = __ldg(&g_col[s0[3] + i]);
                    float v = __ldg(&g_val[s0[3] + i]);
                    float2 x = *(const float2*)&egoIn[c * EMB + lane * 2];
                    a3.x = fmaf(v, x.x, a3.x); a3.y = fmaf(v, x.y, a3.y);
                }
            }
            float* d0 = &sideS[(lr0 + 0) * 65 + lane * 2];
            float* d1 = &sideS[(lr0 + 1) * 65 + lane * 2];
            float* d2 = &sideS[(lr0 + 2) * 65 + lane * 2];
            float* d3 = &sideS[(lr0 + 3) * 65 + lane * 2];
            d0[0] = a0.x; d0[1] = a0.y;
            d1[0] = a1.x; d1[1] = a1.y;
            d2[0] = a2.x; d2[1] = a2.y;
            d3[0] = a3.x; d3[1] = a3.y;
        }
    }
    __syncthreads();

    // ---- Phase B: uS = egoIn(block rows) * sideS
    {
        const float4* eg = (const float4*)&egoIn[(size_t)base * EMB];
#pragma unroll 4
        for (int i = t; i < 2048; i += 256) {
            float4 ev = eg[i];
            int row = i >> 4;
            int c = (i & 15) * 4;
            const float* srow = &sideS[row * 65 + c];
            float* du = &uS[row * 65 + c];
            du[0] = ev.x * srow[0]; du[1] = ev.y * srow[1];
            du[2] = ev.z * srow[2]; du[3] = ev.w * srow[3];
        }
    }
    __syncthreads();

    // ---- Phase C: transform
    int row = t & 127;
    int h   = t >> 7;
    int r   = base + row;

    float o[32];

    if (r < NROWS) {
        const float* srow = &sideS[row * 65];
        const float* urow = &uS[row * 65];

        u64 acc1[16], acc2[16];
#pragma unroll
        for (int j = 0; j < 16; j++) {
            PACK2(acc1[j], b1s[h * 32 + 2 * j], b1s[h * 32 + 2 * j + 1]);
            PACK2(acc2[j], b2s[h * 32 + 2 * j], b2s[h * 32 + 2 * j + 1]);
        }
#pragma unroll 4
        for (int k = 0; k < 64; k++) {
            float s = srow[k];
            float u = urow[k];
            u64 ss, uu;
            PACK2(ss, s, s);
            PACK2(uu, u, u);
            const u64* w1 = (const u64*)&W1s[k * 64 + h * 32];
            const u64* w2 = (const u64*)&W2s[k * 64 + h * 32];
#pragma unroll
            for (int j = 0; j < 16; j += 2) {
                ulonglong2 a = *(const ulonglong2*)&w1[j];
                FMA2(acc1[j],     ss, a.x, acc1[j]);
                FMA2(acc1[j + 1], ss, a.y, acc1[j + 1]);
                ulonglong2 b = *(const ulonglong2*)&w2[j];
                FMA2(acc2[j],     uu, b.x, acc2[j]);
                FMA2(acc2[j + 1], uu, b.y, acc2[j + 1]);
            }
        }

        float sumsq = 0.f;
#pragma unroll
        for (int j = 0; j < 16; j++) {
            float a0, a1, b0, b1;
            UNPACK2(a0, a1, acc1[j]);
            UNPACK2(b0, b1, acc2[j]);
            float o0 = lrelu(a0) + lrelu(b0);
            float o1 = lrelu(a1) + lrelu(b1);
            sumsq += o0 * o0 + o1 * o1;
            o[2 * j]     = o0;
            o[2 * j + 1] = o1;
        }
        ssq[t] = sumsq;

        float4* egor = (float4*)&egoOut[(size_t)r * EMB + h * 32];
#pragma unroll
        for (int j4 = 0; j4 < 8; j4++)
            egor[j4] = make_float4(o[j4 * 4], o[j4 * 4 + 1],
                                   o[j4 * 4 + 2], o[j4 * 4 + 3]);
    }
    __syncthreads();

    if (r < NROWS) {
        float total = ssq[row] + ssq[128 + row];
        float inv = 1.0f / fmaxf(sqrtf(total), 1e-12f);
        float4* orow = (float4*)&out[(size_t)r * (EMB * (NLAYERS + 1))
                                     + (layer + 1) * EMB + h * 32];
#pragma unroll
        for (int j4 = 0; j4 < 8; j4++)
            orow[j4] = make_float4(o[j4 * 4] * inv, o[j4 * 4 + 1] * inv,
                                   o[j4 * 4 + 2] * inv, o[j4 * 4 + 3] * inv);
    }
}

// ---------------------------------------------------------------
extern "C" void kernel_launch(void* const* d_in, const int* in_sizes, int n_in,
                              void* d_out, int out_size) {
    const int*   adj_rows = (const int*)  d_in[0];
    const int*   adj_cols = (const int*)  d_in[1];
    const float* adj_vals = (const float*)d_in[2];
    const float* user_emb = (const float*)d_in[3];
    const float* item_emb = (const float*)d_in[4];
    const float* gc_w     = (const float*)d_in[5];
    const float* gc_b     = (const float*)d_in[6];
    const float* bi_w     = (const float*)d_in[7];
    const float* bi_b     = (const float*)d_in[8];
    float*       out      = (float*)d_out;

    int n_edges = in_sizes[0];

    const int smem_bytes = 25216 * (int)sizeof(float); // 100864
    cudaFuncSetAttribute(k_layer, cudaFuncAttributeMaxDynamicSharedMemorySize, smem_bytes);

    float *egoA = nullptr, *egoB = nullptr;
    cudaGetSymbolAddress((void**)&egoA, g_egoA);
    cudaGetSymbolAddress((void**)&egoB, g_egoB);

    // ---- setup (zero counters + init ego + layer-0 output) ----
    k_setup<<<(NROWS * 16 + 255) / 256, 256>>>(user_emb, item_emb, out);

    // ---- CSR build ----
    k_hist<<<(n_edges + 255) / 256, 256>>>(adj_rows, n_edges);
    k_scan_sums<<<NUM_CHUNKS, 256>>>();
    k_scan_top<<<1, 128>>>();
    k_scan_final<<<NUM_CHUNKS, 256>>>();
    k_scatter<<<(n_edges + 255) / 256, 256>>>(adj_rows, adj_cols, adj_vals, n_edges);

    // ---- fused layers (ping-pong ego buffers) ----
    int tr_blocks = (NROWS + 127) / 128;
    const float* in_p  = egoA;
    float*       out_p = egoB;
    for (int l = 0; l < NLAYERS; l++) {
        k_layer<<<tr_blocks, 256, smem_bytes>>>(
            in_p, out_p,
            gc_w + l * 4096, gc_b + l * 64,
            bi_w + l * 4096, bi_b + l * 64,
            out, l);
        const float* tmp = in_p;
        in_p  = out_p;
        out_p = (float*)tmp;
    }
}

// round 7
// speedup vs baseline: 2.7621x; 2.7621x over previous
#include <cuda_runtime.h>
#include <math.h>

#define NUM_USERS 100000
#define NUM_ITEMS 50000
#define NROWS     150000      // NUM_USERS + NUM_ITEMS
#define NPAD      150016      // padded row count (multiple of 128)
#define EMB       64
#define NEDGES    2400000
#define NLAYERS   3
#define NEG_SLOPE 0.01f

#define SCAN_CHUNK 2048
#define NUM_CHUNKS ((NROWS + SCAN_CHUNK - 1) / SCAN_CHUNK)   // 74

typedef unsigned long long u64;

// packed fp32x2 FMA (Blackwell; ptxas never auto-fuses -> inline PTX)
#define FMA2(d, a, b, c) \
    asm("fma.rn.f32x2 %0, %1, %2, %3;" : "=l"(d) : "l"(a), "l"(b), "l"(c))
#define PACK2(d, lo, hi) \
    asm("mov.b64 %0, {%1, %2};" : "=l"(d) : "f"(lo), "f"(hi))
#define UNPACK2(lo, hi, v) \
    asm("mov.b64 {%0, %1}, %2;" : "=f"(lo), "=f"(hi) : "l"(v))

// -------- persistent device scratch (no allocations allowed) --------
__device__ __align__(16) float g_ego [NPAD * EMB];
__device__ __align__(16) float g_side[NPAD * EMB];
__device__ int   g_row_ptr[NROWS + 1];
__device__ int   g_cursor [NROWS];       // histogram counts, then scatter cursor
__device__ int   g_col [NEDGES];
__device__ float g_val [NEDGES];
__device__ int   g_bsum[NUM_CHUNKS];
__device__ int   g_boff[NUM_CHUNKS];

// ---------------------------------------------------------------
// setup: zero hist counters; ego = [user_emb; item_emb]; out[:,0:64] = ego
// ---------------------------------------------------------------
__global__ void k_setup(const float* __restrict__ user_emb,
                        const float* __restrict__ item_emb,
                        float* __restrict__ out) {
    int idx = blockIdx.x * blockDim.x + threadIdx.x;   // one float4 per thread
    if (idx < NROWS) g_cursor[idx] = 0;
    if (idx >= NROWS * 16) return;
    int r = idx >> 4;
    int c4 = idx & 15;
    float4 v;
    if (r < NUM_USERS)
        v = ((const float4*)&user_emb[r * EMB])[c4];
    else
        v = ((const float4*)&item_emb[(r - NUM_USERS) * EMB])[c4];
    ((float4*)&g_ego[r * EMB])[c4] = v;
    ((float4*)&out[r * (EMB * (NLAYERS + 1))])[c4] = v;
}

// ---------------------------------------------------------------
// CSR build
// ---------------------------------------------------------------
__global__ void k_hist(const int* __restrict__ rows, int n_edges) {
    int e = blockIdx.x * blockDim.x + threadIdx.x;
    if (e < n_edges) atomicAdd(&g_cursor[rows[e]], 1);
}

__global__ void k_scan_sums() {
    int b = blockIdx.x, t = threadIdx.x;
    int base = b * SCAN_CHUNK + t * 8;
    int s = 0;
#pragma unroll
    for (int i = 0; i < 8; i++) {
        int idx = base + i;
        if (idx < NROWS) s += g_cursor[idx];
    }
    __shared__ int sh[256];
    sh[t] = s;
    __syncthreads();
    for (int d = 128; d > 0; d >>= 1) {
        if (t < d) sh[t] += sh[t + d];
        __syncthreads();
    }
    if (t == 0) g_bsum[b] = sh[0];
}

__global__ void k_scan_top() {
    int t = threadIdx.x;
    __shared__ int sh[128];
    int v = (t < NUM_CHUNKS) ? g_bsum[t] : 0;
    sh[t] = v;
    __syncthreads();
    for (int d = 1; d < 128; d <<= 1) {
        int x = (t >= d) ? sh[t - d] : 0;
        __syncthreads();
        sh[t] += x;
        __syncthreads();
    }
    if (t < NUM_CHUNKS) g_boff[t] = sh[t] - v;
    if (t == NUM_CHUNKS - 1) g_row_ptr[NROWS] = sh[t];
}

__global__ void k_scan_final() {
    int b = blockIdx.x, t = threadIdx.x;
    int base = b * SCAN_CHUNK + t * 8;
    int v[8];
    int local = 0;
#pragma unroll
    for (int i = 0; i < 8; i++) {
        int idx = base + i;
        v[i] = (idx < NROWS) ? g_cursor[idx] : 0;
        local += v[i];
    }
    __shared__ int sh[256];
    sh[t] = local;
    __syncthreads();
    for (int d = 1; d < 256; d <<= 1) {
        int x = (t >= d) ? sh[t - d] : 0;
        __syncthreads();
        sh[t] += x;
        __syncthreads();
    }
    int exc = g_boff[b] + (t ? sh[t - 1] : 0);
#pragma unroll
    for (int i = 0; i < 8; i++) {
        int idx = base + i;
        if (idx < NROWS) {
            g_row_ptr[idx] = exc;
            g_cursor[idx]  = exc;
        }
        exc += v[i];
    }
}

__global__ void k_scatter(const int* __restrict__ rows,
                          const int* __restrict__ cols,
                          const float* __restrict__ vals, int n_edges) {
    int e = blockIdx.x * blockDim.x + threadIdx.x;
    if (e < n_edges) {
        int r = rows[e];
        int pos = atomicAdd(&g_cursor[r], 1);
        g_col[pos] = cols[e];
        g_val[pos] = vals[e];
    }
}

// ---------------------------------------------------------------
// SpMM: side = A @ ego  (warp per row, CSR; 4 edges in flight -> MLP 4)
// ---------------------------------------------------------------
__global__ void k_spmm() {
    int w = (blockIdx.x * blockDim.x + threadIdx.x) >> 5;
    int lane = threadIdx.x & 31;
    if (w >= NROWS) return;
    int s = g_row_ptr[w];
    int e = g_row_ptr[w + 1];

    float2 accA = make_float2(0.f, 0.f);
    float2 accB = make_float2(0.f, 0.f);

    int i = s;
    for (; i + 4 <= e; i += 4) {
        // 4 independent (col,val) loads, then 4 independent gathers
        int   c0 = __ldg(&g_col[i]);
        int   c1 = __ldg(&g_col[i + 1]);
        int   c2 = __ldg(&g_col[i + 2]);
        int   c3 = __ldg(&g_col[i + 3]);
        float v0 = __ldg(&g_val[i]);
        float v1 = __ldg(&g_val[i + 1]);
        float v2 = __ldg(&g_val[i + 2]);
        float v3 = __ldg(&g_val[i + 3]);
        float2 x0 = *(const float2*)&g_ego[c0 * EMB + lane * 2];
        float2 x1 = *(const float2*)&g_ego[c1 * EMB + lane * 2];
        float2 x2 = *(const float2*)&g_ego[c2 * EMB + lane * 2];
        float2 x3 = *(const float2*)&g_ego[c3 * EMB + lane * 2];
        accA.x = fmaf(v0, x0.x, accA.x); accA.y = fmaf(v0, x0.y, accA.y);
        accB.x = fmaf(v1, x1.x, accB.x); accB.y = fmaf(v1, x1.y, accB.y);
        accA.x = fmaf(v2, x2.x, accA.x); accA.y = fmaf(v2, x2.y, accA.y);
        accB.x = fmaf(v3, x3.x, accB.x); accB.y = fmaf(v3, x3.y, accB.y);
    }
    for (; i < e; i++) {
        int   c = __ldg(&g_col[i]);
        float v = __ldg(&g_val[i]);
        float2 x = *(const float2*)&g_ego[c * EMB + lane * 2];
        accA.x = fmaf(v, x.x, accA.x);
        accA.y = fmaf(v, x.y, accA.y);
    }
    accA.x += accB.x;
    accA.y += accB.y;
    *(float2*)&g_side[w * EMB + lane * 2] = accA;
}

// ---------------------------------------------------------------
// Transform: ego = lrelu(side@W1+b1) + lrelu((ego*side)@W2+b2)
//            out[:, (l+1)*64 : (l+2)*64] = ego / max(||ego||, eps)
// 256 threads per 128 rows: thread computes 32 output cols of one row.
// (identical to the 577us R3 version)
// ---------------------------------------------------------------
__device__ __forceinline__ float lrelu(float a) {
    return (a > 0.f) ? a : NEG_SLOPE * a;
}

__global__ void __launch_bounds__(256)
k_transform(const float* __restrict__ W1g, const float* __restrict__ b1g,
            const float* __restrict__ W2g, const float* __restrict__ b2g,
            float* __restrict__ out, int layer) {
    extern __shared__ float sh[];
    float* W1s   = sh;                 // 4096
    float* W2s   = sh + 4096;          // 4096
    float* b1s   = sh + 8192;          // 64
    float* b2s   = sh + 8256;          // 64
    float* ssq   = sh + 8320;          // 256
    float* sideS = sh + 8576;          // 128*65 = 8320
    float* uS    = sideS + 128 * 65;   // 8320

    int t = threadIdx.x;
    int base = blockIdx.x * 128;

#pragma unroll 4
    for (int i = t; i < 1024; i += 256) {
        ((float4*)W1s)[i] = ((const float4*)W1g)[i];
        ((float4*)W2s)[i] = ((const float4*)W2g)[i];
    }
    if (t < 64) { b1s[t] = b1g[t]; b2s[t] = b2g[t]; }

    const float4* sg = (const float4*)&g_side[(size_t)base * EMB];
    const float4* eg = (const float4*)&g_ego [(size_t)base * EMB];
#pragma unroll 4
    for (int i = t; i < 2048; i += 256) {
        float4 sv = sg[i];
        float4 ev = eg[i];
        int row = i >> 4;
        int c = (i & 15) * 4;
        float* ds = &sideS[row * 65 + c];
        float* du = &uS   [row * 65 + c];
        ds[0] = sv.x; ds[1] = sv.y; ds[2] = sv.z; ds[3] = sv.w;
        du[0] = ev.x * sv.x; du[1] = ev.y * sv.y;
        du[2] = ev.z * sv.z; du[3] = ev.w * sv.w;
    }
    __syncthreads();

    int row = t & 127;
    int h   = t >> 7;
    int r   = base + row;

    float o[32];

    if (r < NROWS) {
        const float* srow = &sideS[row * 65];
        const float* urow = &uS[row * 65];

        u64 acc1[16], acc2[16];
#pragma unroll
        for (int j = 0; j < 16; j++) {
            PACK2(acc1[j], b1s[h * 32 + 2 * j], b1s[h * 32 + 2 * j + 1]);
            PACK2(acc2[j], b2s[h * 32 + 2 * j], b2s[h * 32 + 2 * j + 1]);
        }
#pragma unroll 4
        for (int k = 0; k < 64; k++) {
            float s = srow[k];
            float u = urow[k];
            u64 ss, uu;
            PACK2(ss, s, s);
            PACK2(uu, u, u);
            const u64* w1 = (const u64*)&W1s[k * 64 + h * 32];
            const u64* w2 = (const u64*)&W2s[k * 64 + h * 32];
#pragma unroll
            for (int j = 0; j < 16; j += 2) {
                ulonglong2 a = *(const ulonglong2*)&w1[j];
                FMA2(acc1[j],     ss, a.x, acc1[j]);
                FMA2(acc1[j + 1], ss, a.y, acc1[j + 1]);
                ulonglong2 b = *(const ulonglong2*)&w2[j];
                FMA2(acc2[j],     uu, b.x, acc2[j]);
                FMA2(acc2[j + 1], uu, b.y, acc2[j + 1]);
            }
        }

        float sumsq = 0.f;
#pragma unroll
        for (int j = 0; j < 16; j++) {
            float a0, a1, b0, b1;
            UNPACK2(a0, a1, acc1[j]);
            UNPACK2(b0, b1, acc2[j]);
            float o0 = lrelu(a0) + lrelu(b0);
            float o1 = lrelu(a1) + lrelu(b1);
            sumsq += o0 * o0 + o1 * o1;
            o[2 * j]     = o0;
            o[2 * j + 1] = o1;
        }
        ssq[t] = sumsq;

        float4* egor = (float4*)&g_ego[(size_t)r * EMB + h * 32];
#pragma unroll
        for (int j4 = 0; j4 < 8; j4++)
            egor[j4] = make_float4(o[j4 * 4], o[j4 * 4 + 1],
                                   o[j4 * 4 + 2], o[j4 * 4 + 3]);
    }
    __syncthreads();

    if (r < NROWS) {
        float total = ssq[row] + ssq[128 + row];
        float inv = 1.0f / fmaxf(sqrtf(total), 1e-12f);
        float4* orow = (float4*)&out[(size_t)r * (EMB * (NLAYERS + 1))
                                     + (layer + 1) * EMB + h * 32];
#pragma unroll
        for (int j4 = 0; j4 < 8; j4++)
            orow[j4] = make_float4(o[j4 * 4] * inv, o[j4 * 4 + 1] * inv,
                                   o[j4 * 4 + 2] * inv, o[j4 * 4 + 3] * inv);
    }
}

// ---------------------------------------------------------------
extern "C" void kernel_launch(void* const* d_in, const int* in_sizes, int n_in,
                              void* d_out, int out_size) {
    const int*   adj_rows = (const int*)  d_in[0];
    const int*   adj_cols = (const int*)  d_in[1];
    const float* adj_vals = (const float*)d_in[2];
    const float* user_emb = (const float*)d_in[3];
    const float* item_emb = (const float*)d_in[4];
    const float* gc_w     = (const float*)d_in[5];
    const float* gc_b     = (const float*)d_in[6];
    const float* bi_w     = (const float*)d_in[7];
    const float* bi_b     = (const float*)d_in[8];
    float*       out      = (float*)d_out;

    int n_edges = in_sizes[0];

    const int smem_bytes = 25216 * (int)sizeof(float); // 100864
    cudaFuncSetAttribute(k_transform, cudaFuncAttributeMaxDynamicSharedMemorySize, smem_bytes);

    // ---- setup (zero counters + init ego + layer-0 output) ----
    k_setup<<<(NROWS * 16 + 255) / 256, 256>>>(user_emb, item_emb, out);

    // ---- CSR build ----
    k_hist<<<(n_edges + 255) / 256, 256>>>(adj_rows, n_edges);
    k_scan_sums<<<NUM_CHUNKS, 256>>>();
    k_scan_top<<<1, 128>>>();
    k_scan_final<<<NUM_CHUNKS, 256>>>();
    k_scatter<<<(n_edges + 255) / 256, 256>>>(adj_rows, adj_cols, adj_vals, n_edges);

    // ---- layers ----
    int spmm_blocks = (NROWS * 32 + 255) / 256;        // warp per row
    int tr_blocks   = (NROWS + 127) / 128;
    for (int l = 0; l < NLAYERS; l++) {
        k_spmm<<<spmm_blocks, 256>>>();
        k_transform<<<tr_blocks, 256, smem_bytes>>>(
            gc_w + l * 4096, gc_b + l * 64,
            bi_w + l * 4096, bi_b + l * 64,
            out, l);
    }
}